// round 5
// baseline (speedup 1.0000x reference)
#include <cuda_runtime.h>
#include <math.h>

#define NN_MAX 50000
#define NE_MAX 800000
#define SCAN_B 1024

typedef unsigned long long ull;

// ---------------- f32x2 packed helpers (sm_103a) ----------------
__device__ __forceinline__ ull fma2(ull a, ull b, ull c) {
    ull d;
    asm("fma.rn.f32x2 %0, %1, %2, %3;" : "=l"(d) : "l"(a), "l"(b), "l"(c));
    return d;
}
__device__ __forceinline__ ull pack2(float x) {
    ull d;
    unsigned int u = __float_as_uint(x);
    asm("mov.b64 %0, {%1, %2};" : "=l"(d) : "r"(u), "r"(u));
    return d;
}
__device__ __forceinline__ float2 unpack2(ull v) {
    unsigned int lo, hi;
    asm("mov.b64 {%0, %1}, %2;" : "=r"(lo), "=r"(hi) : "l"(v));
    return make_float2(__uint_as_float(lo), __uint_as_float(hi));
}

// ---------------- device scratch (static, allocation-free) ----------------
__device__ float g_Z[(size_t)NN_MAX * 128];
__device__ float g_H[(size_t)NN_MAX * 128];
__device__ float g_dinv[NN_MAX];
__device__ int   g_count[NN_MAX];
__device__ int   g_cursor[NN_MAX];
__device__ int   g_off[NN_MAX + 1];
__device__ int   g_src[NE_MAX];
__device__ float g_w[NE_MAX];
__device__ int   g_blk[64];
__device__ int   g_is64;

__device__ __forceinline__ int edge_val(const void* ei, int E, int which, int e) {
    if (g_is64) return (int)((const long long*)ei)[(size_t)which * E + e];
    return ((const int*)ei)[(size_t)which * E + e];
}

// int64 detection: high words of small nonneg int64 are all zero.
__global__ void detect_k(const int* __restrict__ ei) {
    __shared__ int any;
    if (threadIdx.x == 0) any = 0;
    __syncthreads();
    int local = 0;
    for (int i = threadIdx.x; i < 1024; i += blockDim.x)
        if (ei[2 * i + 1] != 0) local = 1;
    if (local) atomicOr(&any, 1);
    __syncthreads();
    if (threadIdx.x == 0) g_is64 = any ? 0 : 1;
}

__global__ void init_k(int n) {
    int i = blockIdx.x * blockDim.x + threadIdx.x;
    if (i < n) { g_count[i] = 0; g_cursor[i] = 0; }
}

__global__ void count_k(const void* __restrict__ ei, int E) {
    int e = blockIdx.x * blockDim.x + threadIdx.x;
    if (e < E) atomicAdd(&g_count[edge_val(ei, E, 1, e)], 1);
}

__global__ void scan1_k(int n) {
    __shared__ int sh[SCAN_B];
    int i = blockIdx.x * SCAN_B + threadIdx.x;
    int v = (i < n) ? g_count[i] : 0;
    if (i < n) g_dinv[i] = rsqrtf((float)(v + 1));
    sh[threadIdx.x] = v;
    __syncthreads();
    for (int off = 1; off < SCAN_B; off <<= 1) {
        int t = (threadIdx.x >= off) ? sh[threadIdx.x - off] : 0;
        __syncthreads();
        sh[threadIdx.x] += t;
        __syncthreads();
    }
    if (i < n) g_off[i] = sh[threadIdx.x] - v;
    if (threadIdx.x == SCAN_B - 1) g_blk[blockIdx.x] = sh[SCAN_B - 1];
}

__global__ void scan2_k(int nb) {
    __shared__ int sh[64];
    int t = threadIdx.x;
    sh[t] = (t < nb) ? g_blk[t] : 0;
    __syncthreads();
    for (int off = 1; off < 64; off <<= 1) {
        int v = (t >= off) ? sh[t - off] : 0;
        __syncthreads();
        sh[t] += v;
        __syncthreads();
    }
    g_blk[t] = sh[t];
}

__global__ void scan3_k(int n, int nb) {
    int i = blockIdx.x * blockDim.x + threadIdx.x;
    if (i < n) {
        int blk = i >> 10;
        if (blk > 0) g_off[i] += g_blk[blk - 1];
    }
    if (i == 0) g_off[n] = g_blk[nb - 1];
}

__global__ void fill_k(const void* __restrict__ ei, int E) {
    int e = blockIdx.x * blockDim.x + threadIdx.x;
    if (e < E) {
        int dst = edge_val(ei, E, 1, e);
        int src = edge_val(ei, E, 0, e);
        int p = g_off[dst] + atomicAdd(&g_cursor[dst], 1);
        g_src[p] = src;
        g_w[p] = g_dinv[src] * g_dinv[dst];
    }
}

__global__ void ycopy_k(const void* __restrict__ y, float* __restrict__ out,
                        int n, int out_size) {
    int i = blockIdx.x * blockDim.x + threadIdx.x;
    if (i < n && out_size >= 2 * n) {
        float yv = g_is64 ? (float)((const long long*)y)[i]
                          : (float)((const int*)y)[i];
        out[n + i] = yv;
    }
}

// ---------------- f32x2 SIMT GEMM: C[M,N] = A[M,K] @ W[K,N] ----------------
// 256 threads = 8 warps; each warp computes 8 rows; lane covers N/32 cols.
template<int K, int N>
__global__ void __launch_bounds__(256) gemm_k(const float* __restrict__ A,
                                              const float* __restrict__ W,
                                              float* __restrict__ C, int M) {
    constexpr int CP = N / 32;          // 4 or 2 cols per lane
    constexpr int PR = CP / 2;          // f32x2 pairs per lane (2 or 1)
    constexpr int KC = (K * N <= 8192) ? K : (8192 / N);
    __shared__ float sW[KC * N];
    int warp = threadIdx.x >> 5, lane = threadIdx.x & 31;
    int r0 = (blockIdx.x * 8 + warp) * 8;

    ull acc[8][PR];
#pragma unroll
    for (int r = 0; r < 8; r++)
#pragma unroll
        for (int p = 0; p < PR; p++) acc[r][p] = 0ULL;

    for (int kc = 0; kc < K; kc += KC) {
        __syncthreads();
        {
            const float4* Wv = (const float4*)(W + (size_t)kc * N);
            float4* sWv = (float4*)sW;
            for (int i = threadIdx.x; i < KC * N / 4; i += 256) sWv[i] = Wv[i];
        }
        __syncthreads();
        if (r0 < M) {
            int rr[8];
#pragma unroll
            for (int r = 0; r < 8; r++) { int v = r0 + r; rr[r] = v < M ? v : M - 1; }
#pragma unroll 2
            for (int kk = 0; kk < KC; kk += 4) {
                float4 a[8];
#pragma unroll
                for (int r = 0; r < 8; r++)
                    a[r] = *(const float4*)(A + (size_t)rr[r] * K + kc + kk);
#pragma unroll
                for (int t = 0; t < 4; t++) {
                    const ull* wp = (const ull*)&sW[(kk + t) * N + lane * CP];
                    ull w0 = wp[0];
                    ull w1 = (PR == 2) ? wp[1] : 0ULL;
#pragma unroll
                    for (int r = 0; r < 8; r++) {
                        float av = (t == 0) ? a[r].x : (t == 1) ? a[r].y
                                 : (t == 2) ? a[r].z : a[r].w;
                        ull av2 = pack2(av);
                        acc[r][0] = fma2(av2, w0, acc[r][0]);
                        if (PR == 2) acc[r][1] = fma2(av2, w1, acc[r][1]);
                    }
                }
            }
        }
    }
#pragma unroll
    for (int r = 0; r < 8; r++) {
        if (r0 + r < M) {
            ull* cp = (ull*)(C + (size_t)(r0 + r) * N + lane * CP);
            cp[0] = acc[r][0];
            if (PR == 2) cp[1] = acc[r][1];
        }
    }
}

// ---------------- edge aggregation: H[i] = relu(sum_e w_e * Z[src] + b) ----
template<int N>
__global__ void agg_k(const float* __restrict__ Z, float* __restrict__ H,
                      const float* __restrict__ b, int n) {
    constexpr int CP = N / 32;
    int node = (blockIdx.x * blockDim.x + threadIdx.x) >> 5;
    int lane = threadIdx.x & 31;
    if (node >= n) return;
    float di = g_dinv[node];
    float acc[CP];
    {
        float w = di * di;  // self loop
        const float* zp = Z + (size_t)node * N + lane * CP;
        if (CP == 4) {
            float4 zv = *(const float4*)zp;
            acc[0] = w * zv.x; acc[1] = w * zv.y;
            acc[2] = w * zv.z; acc[3] = w * zv.w;
        } else {
            float2 zv = *(const float2*)zp;
            acc[0] = w * zv.x; acc[1] = w * zv.y;
        }
    }
    int e = g_off[node], end = g_off[node + 1];
    // 4-edge unroll: 4 independent gathers in flight
    for (; e + 4 <= end; e += 4) {
        int s0 = g_src[e], s1 = g_src[e + 1], s2 = g_src[e + 2], s3 = g_src[e + 3];
        float w0 = g_w[e], w1 = g_w[e + 1], w2 = g_w[e + 2], w3 = g_w[e + 3];
        if (CP == 4) {
            float4 a0 = *(const float4*)(Z + (size_t)s0 * N + lane * 4);
            float4 a1 = *(const float4*)(Z + (size_t)s1 * N + lane * 4);
            float4 a2 = *(const float4*)(Z + (size_t)s2 * N + lane * 4);
            float4 a3 = *(const float4*)(Z + (size_t)s3 * N + lane * 4);
            acc[0] = fmaf(w0, a0.x, acc[0]); acc[1] = fmaf(w0, a0.y, acc[1]);
            acc[2] = fmaf(w0, a0.z, acc[2]); acc[3] = fmaf(w0, a0.w, acc[3]);
            acc[0] = fmaf(w1, a1.x, acc[0]); acc[1] = fmaf(w1, a1.y, acc[1]);
            acc[2] = fmaf(w1, a1.z, acc[2]); acc[3] = fmaf(w1, a1.w, acc[3]);
            acc[0] = fmaf(w2, a2.x, acc[0]); acc[1] = fmaf(w2, a2.y, acc[1]);
            acc[2] = fmaf(w2, a2.z, acc[2]); acc[3] = fmaf(w2, a2.w, acc[3]);
            acc[0] = fmaf(w3, a3.x, acc[0]); acc[1] = fmaf(w3, a3.y, acc[1]);
            acc[2] = fmaf(w3, a3.z, acc[2]); acc[3] = fmaf(w3, a3.w, acc[3]);
        } else {
            float2 a0 = *(const float2*)(Z + (size_t)s0 * N + lane * 2);
            float2 a1 = *(const float2*)(Z + (size_t)s1 * N + lane * 2);
            float2 a2 = *(const float2*)(Z + (size_t)s2 * N + lane * 2);
            float2 a3 = *(const float2*)(Z + (size_t)s3 * N + lane * 2);
            acc[0] = fmaf(w0, a0.x, acc[0]); acc[1] = fmaf(w0, a0.y, acc[1]);
            acc[0] = fmaf(w1, a1.x, acc[0]); acc[1] = fmaf(w1, a1.y, acc[1]);
            acc[0] = fmaf(w2, a2.x, acc[0]); acc[1] = fmaf(w2, a2.y, acc[1]);
            acc[0] = fmaf(w3, a3.x, acc[0]); acc[1] = fmaf(w3, a3.y, acc[1]);
        }
    }
    for (; e < end; e++) {
        int s = g_src[e];
        float w = g_w[e];
        const float* zp = Z + (size_t)s * N + lane * CP;
        if (CP == 4) {
            float4 zv = *(const float4*)zp;
            acc[0] = fmaf(w, zv.x, acc[0]); acc[1] = fmaf(w, zv.y, acc[1]);
            acc[2] = fmaf(w, zv.z, acc[2]); acc[3] = fmaf(w, zv.w, acc[3]);
        } else {
            float2 zv = *(const float2*)zp;
            acc[0] = fmaf(w, zv.x, acc[0]); acc[1] = fmaf(w, zv.y, acc[1]);
        }
    }
#pragma unroll
    for (int j = 0; j < CP; j++) {
        float v = acc[j] + __ldg(&b[lane * CP + j]);
        H[(size_t)node * N + lane * CP + j] = v > 0.f ? v : 0.f;
    }
}

// ---------------- prototype distances + MLP readout + sigmoid ---------
__global__ void final_k(const float* __restrict__ H, const float* __restrict__ prot,
                        const float* __restrict__ Wf0, const float* __restrict__ bf0,
                        const float* __restrict__ Wf1, const float* __restrict__ bf1,
                        float* __restrict__ out, int n) {
    __shared__ float sP[16 * 64];
    __shared__ float sPsq[16];
    __shared__ float sW0[16 * 8];
    __shared__ float sb0[8];
    __shared__ float sW1[8];
    __shared__ float sb1;
    for (int i = threadIdx.x; i < 16 * 64; i += blockDim.x) sP[i] = prot[i];
    if (threadIdx.x < 16 * 8) sW0[threadIdx.x] = Wf0[threadIdx.x];
    if (threadIdx.x < 8) { sb0[threadIdx.x] = bf0[threadIdx.x]; sW1[threadIdx.x] = Wf1[threadIdx.x]; }
    if (threadIdx.x == 0) sb1 = bf1[0];
    __syncthreads();
    if (threadIdx.x < 16) {
        float s = 0.f;
        for (int k = 0; k < 64; k++) { float p = sP[threadIdx.x * 64 + k]; s += p * p; }
        sPsq[threadIdx.x] = s;
    }
    __syncthreads();

    int i = blockIdx.x * blockDim.x + threadIdx.x;
    if (i >= n) return;

    // packed-pair dot products along k (sP rows 8B-aligned)
    ull dot2[16];
#pragma unroll
    for (int j = 0; j < 16; j++) dot2[j] = 0ULL;
    ull hh2 = 0ULL;
    const ull* h2p = (const ull*)(H + (size_t)i * 64);
    const ull* sP2 = (const ull*)sP;
#pragma unroll 4
    for (int kk = 0; kk < 32; kk++) {
        ull h2 = h2p[kk];
        hh2 = fma2(h2, h2, hh2);
#pragma unroll
        for (int j = 0; j < 16; j++)
            dot2[j] = fma2(h2, sP2[j * 32 + kk], dot2[j]);
    }
    float2 hp = unpack2(hh2);
    float hh = hp.x + hp.y;
    float sim[16];
#pragma unroll
    for (int j = 0; j < 16; j++) {
        float2 dp = unpack2(dot2[j]);
        float d2 = hh + sPsq[j] - 2.f * (dp.x + dp.y);
        d2 = d2 > 0.f ? d2 : 0.f;
        sim[j] = logf((d2 + 1.0f) / (d2 + 1e-4f));
    }
    float o = sb1;
#pragma unroll
    for (int m = 0; m < 8; m++) {
        float t = sb0[m];
#pragma unroll
        for (int j = 0; j < 16; j++) t = fmaf(sim[j], sW0[j * 8 + m], t);
        float z = 0.5f * t * (1.0f + erff(t * 0.70710678118654752f));  // exact GELU
        o = fmaf(z, sW1[m], o);
    }
    out[i] = 1.0f / (1.0f + expf(-o));
}

// ---------------- launch ----------------
extern "C" void kernel_launch(void* const* d_in, const int* in_sizes, int n_in,
                              void* d_out, int out_size) {
    const float* x    = (const float*)d_in[0];
    const void*  ei   = d_in[1];
    const void*  y    = d_in[2];
    const float* W1   = (const float*)d_in[3];
    const float* b1   = (const float*)d_in[4];
    const float* W2   = (const float*)d_in[5];
    const float* b2   = (const float*)d_in[6];
    const float* W3   = (const float*)d_in[7];
    const float* b3   = (const float*)d_in[8];
    const float* prot = (const float*)d_in[9];
    const float* Wf0  = (const float*)d_in[10];
    const float* bf0  = (const float*)d_in[11];
    const float* Wf1  = (const float*)d_in[12];
    const float* bf1  = (const float*)d_in[13];
    float* out = (float*)d_out;

    int n = in_sizes[0] / 128;
    int E = in_sizes[1] / 2;
    int nb = (n + SCAN_B - 1) / SCAN_B;

    void *pZ, *pH;
    cudaGetSymbolAddress(&pZ, g_Z);
    cudaGetSymbolAddress(&pH, g_H);
    float* Z = (float*)pZ;
    float* H = (float*)pH;

    // ---- fork: CSR build + y copy on side stream, gemm1 on main ----
    cudaStream_t s2;
    cudaStreamCreateWithFlags(&s2, cudaStreamNonBlocking);
    cudaEvent_t evFork, evJoin;
    cudaEventCreateWithFlags(&evFork, cudaEventDisableTiming);
    cudaEventCreateWithFlags(&evJoin, cudaEventDisableTiming);

    cudaEventRecord(evFork, 0);
    cudaStreamWaitEvent(s2, evFork, 0);

    detect_k<<<1, 256, 0, s2>>>((const int*)ei);
    init_k<<<(n + 255) / 256, 256, 0, s2>>>(n);
    count_k<<<(E + 255) / 256, 256, 0, s2>>>(ei, E);
    scan1_k<<<nb, SCAN_B, 0, s2>>>(n);
    scan2_k<<<1, 64, 0, s2>>>(nb);
    scan3_k<<<(n + 255) / 256, 256, 0, s2>>>(n, nb);
    fill_k<<<(E + 255) / 256, 256, 0, s2>>>(ei, E);
    ycopy_k<<<(n + 255) / 256, 256, 0, s2>>>(y, out, n, out_size);

    int gemm_grid = (n + 63) / 64;           // 8 warps * 8 rows per block
    int agg_grid  = (n + 7) / 8;

    gemm_k<128, 128><<<gemm_grid, 256>>>(x, W1, Z, n);   // main stream

    cudaEventRecord(evJoin, s2);
    cudaStreamWaitEvent(0, evJoin, 0);

    agg_k<128><<<agg_grid, 256>>>(Z, H, b1, n);
    gemm_k<128, 64><<<gemm_grid, 256>>>(H, W2, Z, n);
    agg_k<64><<<agg_grid, 256>>>(Z, H, b2, n);
    gemm_k<64, 64><<<gemm_grid, 256>>>(H, W3, Z, n);
    agg_k<64><<<agg_grid, 256>>>(Z, H, b3, n);

    final_k<<<(n + 127) / 128, 128>>>(H, prot, Wf0, bf0, Wf1, bf1, out, n);
}

// round 6
// speedup vs baseline: 1.3280x; 1.3280x over previous
#include <cuda_runtime.h>
#include <math.h>

#define NN_MAX 50000
#define NE_MAX 800000
#define SCAN_B 1024

typedef unsigned long long ull;

// ---------------- f32x2 packed helpers (sm_103a) ----------------
__device__ __forceinline__ ull fma2(ull a, ull b, ull c) {
    ull d;
    asm("fma.rn.f32x2 %0, %1, %2, %3;" : "=l"(d) : "l"(a), "l"(b), "l"(c));
    return d;
}
__device__ __forceinline__ ull pack2(float x) {
    ull d;
    unsigned int u = __float_as_uint(x);
    asm("mov.b64 %0, {%1, %2};" : "=l"(d) : "r"(u), "r"(u));
    return d;
}

// ---------------- device scratch (static, allocation-free) ----------------
__device__ float g_Z[(size_t)NN_MAX * 128];
__device__ float g_H[(size_t)NN_MAX * 128];
__device__ float g_dinv[NN_MAX];
__device__ int   g_count[NN_MAX];
__device__ int   g_cursor[NN_MAX];
__device__ int   g_off[NN_MAX + 1];
__device__ int   g_src[NE_MAX];
__device__ float g_w[NE_MAX];
__device__ int   g_blk[64];
__device__ int   g_is64;

__device__ __forceinline__ int edge_val(const void* ei, int E, int which, int e) {
    if (g_is64) return (int)((const long long*)ei)[(size_t)which * E + e];
    return ((const int*)ei)[(size_t)which * E + e];
}

__global__ void detect_k(const int* __restrict__ ei) {
    __shared__ int any;
    if (threadIdx.x == 0) any = 0;
    __syncthreads();
    int local = 0;
    for (int i = threadIdx.x; i < 1024; i += blockDim.x)
        if (ei[2 * i + 1] != 0) local = 1;
    if (local) atomicOr(&any, 1);
    __syncthreads();
    if (threadIdx.x == 0) g_is64 = any ? 0 : 1;
}

__global__ void init_k(int n) {
    int i = blockIdx.x * blockDim.x + threadIdx.x;
    if (i < n) { g_count[i] = 0; g_cursor[i] = 0; }
}

__global__ void count_k(const void* __restrict__ ei, int E) {
    int e = blockIdx.x * blockDim.x + threadIdx.x;
    if (e < E) atomicAdd(&g_count[edge_val(ei, E, 1, e)], 1);
}

__global__ void scan1_k(int n) {
    __shared__ int sh[SCAN_B];
    int i = blockIdx.x * SCAN_B + threadIdx.x;
    int v = (i < n) ? g_count[i] : 0;
    if (i < n) g_dinv[i] = rsqrtf((float)(v + 1));
    sh[threadIdx.x] = v;
    __syncthreads();
    for (int off = 1; off < SCAN_B; off <<= 1) {
        int t = (threadIdx.x >= off) ? sh[threadIdx.x - off] : 0;
        __syncthreads();
        sh[threadIdx.x] += t;
        __syncthreads();
    }
    if (i < n) g_off[i] = sh[threadIdx.x] - v;
    if (threadIdx.x == SCAN_B - 1) g_blk[blockIdx.x] = sh[SCAN_B - 1];
}

__global__ void scan2_k(int nb) {
    __shared__ int sh[64];
    int t = threadIdx.x;
    sh[t] = (t < nb) ? g_blk[t] : 0;
    __syncthreads();
    for (int off = 1; off < 64; off <<= 1) {
        int v = (t >= off) ? sh[t - off] : 0;
        __syncthreads();
        sh[t] += v;
        __syncthreads();
    }
    g_blk[t] = sh[t];
}

__global__ void scan3_k(int n, int nb) {
    int i = blockIdx.x * blockDim.x + threadIdx.x;
    if (i < n) {
        int blk = i >> 10;
        if (blk > 0) g_off[i] += g_blk[blk - 1];
    }
    if (i == 0) g_off[n] = g_blk[nb - 1];
}

__global__ void fill_k(const void* __restrict__ ei, int E) {
    int e = blockIdx.x * blockDim.x + threadIdx.x;
    if (e < E) {
        int dst = edge_val(ei, E, 1, e);
        int src = edge_val(ei, E, 0, e);
        int p = g_off[dst] + atomicAdd(&g_cursor[dst], 1);
        g_src[p] = src;
        g_w[p] = g_dinv[src] * g_dinv[dst];
    }
}

// ---------------- f32x2 SIMT GEMM: C[M,N] = A[M,K] @ W[K,N] ----------------
// R4 shape: 256 threads = 8 warps, 4 rows per warp; arithmetic via FFMA2.
template<int K, int N>
__global__ void __launch_bounds__(256) gemm_k(const float* __restrict__ A,
                                              const float* __restrict__ W,
                                              float* __restrict__ C, int M) {
    constexpr int CP = N / 32;          // cols per lane (4 or 2)
    constexpr int PR = CP / 2;          // f32x2 pairs per lane (2 or 1)
    constexpr int KC = (K * N <= 8192) ? K : (8192 / N);
    __shared__ float sW[KC * N];
    int warp = threadIdx.x >> 5, lane = threadIdx.x & 31;
    int r0 = (blockIdx.x * 8 + warp) * 4;

    ull acc[4][PR];
#pragma unroll
    for (int r = 0; r < 4; r++)
#pragma unroll
        for (int p = 0; p < PR; p++) acc[r][p] = 0ULL;

    for (int kc = 0; kc < K; kc += KC) {
        __syncthreads();
        {
            const float4* Wv = (const float4*)(W + (size_t)kc * N);
            float4* sWv = (float4*)sW;
            for (int i = threadIdx.x; i < KC * N / 4; i += 256) sWv[i] = Wv[i];
        }
        __syncthreads();
        if (r0 < M) {
            int rr[4];
#pragma unroll
            for (int r = 0; r < 4; r++) { int v = r0 + r; rr[r] = v < M ? v : M - 1; }
#pragma unroll 2
            for (int kk = 0; kk < KC; kk += 4) {
                float4 a[4];
#pragma unroll
                for (int r = 0; r < 4; r++)
                    a[r] = *(const float4*)(A + (size_t)rr[r] * K + kc + kk);
#pragma unroll
                for (int t = 0; t < 4; t++) {
                    const ull* wp = (const ull*)&sW[(kk + t) * N + lane * CP];
                    ull w0 = wp[0];
                    ull w1 = (PR == 2) ? wp[1] : 0ULL;
#pragma unroll
                    for (int r = 0; r < 4; r++) {
                        float av = (t == 0) ? a[r].x : (t == 1) ? a[r].y
                                 : (t == 2) ? a[r].z : a[r].w;
                        ull av2 = pack2(av);
                        acc[r][0] = fma2(av2, w0, acc[r][0]);
                        if (PR == 2) acc[r][1] = fma2(av2, w1, acc[r][1]);
                    }
                }
            }
        }
    }
#pragma unroll
    for (int r = 0; r < 4; r++) {
        if (r0 + r < M) {
            ull* cp = (ull*)(C + (size_t)(r0 + r) * N + lane * CP);
            cp[0] = acc[r][0];
            if (PR == 2) cp[1] = acc[r][1];
        }
    }
}

// ---------------- edge aggregation: H[i] = relu(sum_e w_e * Z[src] + b) ----
template<int N>
__global__ void agg_k(const float* __restrict__ Z, float* __restrict__ H,
                      const float* __restrict__ b, int n) {
    constexpr int CP = N / 32;
    int node = (blockIdx.x * blockDim.x + threadIdx.x) >> 5;
    int lane = threadIdx.x & 31;
    if (node >= n) return;
    float di = g_dinv[node];
    float acc[CP];
    {
        float w = di * di;  // self loop
        const float* zp = Z + (size_t)node * N + lane * CP;
        if (CP == 4) {
            float4 zv = *(const float4*)zp;
            acc[0] = w * zv.x; acc[1] = w * zv.y;
            acc[2] = w * zv.z; acc[3] = w * zv.w;
        } else {
            float2 zv = *(const float2*)zp;
            acc[0] = w * zv.x; acc[1] = w * zv.y;
        }
    }
    int e = g_off[node], end = g_off[node + 1];
    for (; e + 4 <= end; e += 4) {
        int s0 = g_src[e], s1 = g_src[e + 1], s2 = g_src[e + 2], s3 = g_src[e + 3];
        float w0 = g_w[e], w1 = g_w[e + 1], w2 = g_w[e + 2], w3 = g_w[e + 3];
        if (CP == 4) {
            float4 a0 = *(const float4*)(Z + (size_t)s0 * N + lane * 4);
            float4 a1 = *(const float4*)(Z + (size_t)s1 * N + lane * 4);
            float4 a2 = *(const float4*)(Z + (size_t)s2 * N + lane * 4);
            float4 a3 = *(const float4*)(Z + (size_t)s3 * N + lane * 4);
            acc[0] = fmaf(w0, a0.x, acc[0]); acc[1] = fmaf(w0, a0.y, acc[1]);
            acc[2] = fmaf(w0, a0.z, acc[2]); acc[3] = fmaf(w0, a0.w, acc[3]);
            acc[0] = fmaf(w1, a1.x, acc[0]); acc[1] = fmaf(w1, a1.y, acc[1]);
            acc[2] = fmaf(w1, a1.z, acc[2]); acc[3] = fmaf(w1, a1.w, acc[3]);
            acc[0] = fmaf(w2, a2.x, acc[0]); acc[1] = fmaf(w2, a2.y, acc[1]);
            acc[2] = fmaf(w2, a2.z, acc[2]); acc[3] = fmaf(w2, a2.w, acc[3]);
            acc[0] = fmaf(w3, a3.x, acc[0]); acc[1] = fmaf(w3, a3.y, acc[1]);
            acc[2] = fmaf(w3, a3.z, acc[2]); acc[3] = fmaf(w3, a3.w, acc[3]);
        } else {
            float2 a0 = *(const float2*)(Z + (size_t)s0 * N + lane * 2);
            float2 a1 = *(const float2*)(Z + (size_t)s1 * N + lane * 2);
            float2 a2 = *(const float2*)(Z + (size_t)s2 * N + lane * 2);
            float2 a3 = *(const float2*)(Z + (size_t)s3 * N + lane * 2);
            acc[0] = fmaf(w0, a0.x, acc[0]); acc[1] = fmaf(w0, a0.y, acc[1]);
            acc[0] = fmaf(w1, a1.x, acc[0]); acc[1] = fmaf(w1, a1.y, acc[1]);
            acc[0] = fmaf(w2, a2.x, acc[0]); acc[1] = fmaf(w2, a2.y, acc[1]);
            acc[0] = fmaf(w3, a3.x, acc[0]); acc[1] = fmaf(w3, a3.y, acc[1]);
        }
    }
    for (; e < end; e++) {
        int s = g_src[e];
        float w = g_w[e];
        const float* zp = Z + (size_t)s * N + lane * CP;
        if (CP == 4) {
            float4 zv = *(const float4*)zp;
            acc[0] = fmaf(w, zv.x, acc[0]); acc[1] = fmaf(w, zv.y, acc[1]);
            acc[2] = fmaf(w, zv.z, acc[2]); acc[3] = fmaf(w, zv.w, acc[3]);
        } else {
            float2 zv = *(const float2*)zp;
            acc[0] = fmaf(w, zv.x, acc[0]); acc[1] = fmaf(w, zv.y, acc[1]);
        }
    }
#pragma unroll
    for (int j = 0; j < CP; j++) {
        float v = acc[j] + __ldg(&b[lane * CP + j]);
        H[(size_t)node * N + lane * CP + j] = v > 0.f ? v : 0.f;
    }
}

// ---------------- prototype distances + MLP readout + sigmoid + y ---------
__global__ void final_k(const float* __restrict__ H, const float* __restrict__ prot,
                        const float* __restrict__ Wf0, const float* __restrict__ bf0,
                        const float* __restrict__ Wf1, const float* __restrict__ bf1,
                        const void* __restrict__ y,
                        float* __restrict__ out, int n, int out_size) {
    __shared__ float sP[16 * 64];
    __shared__ float sPsq[16];
    __shared__ float sW0[16 * 8];
    __shared__ float sb0[8];
    __shared__ float sW1[8];
    __shared__ float sb1;
    for (int i = threadIdx.x; i < 16 * 64; i += blockDim.x) sP[i] = prot[i];
    if (threadIdx.x < 16 * 8) sW0[threadIdx.x] = Wf0[threadIdx.x];
    if (threadIdx.x < 8) { sb0[threadIdx.x] = bf0[threadIdx.x]; sW1[threadIdx.x] = Wf1[threadIdx.x]; }
    if (threadIdx.x == 0) sb1 = bf1[0];
    __syncthreads();
    if (threadIdx.x < 16) {
        float s = 0.f;
        for (int k = 0; k < 64; k++) { float p = sP[threadIdx.x * 64 + k]; s += p * p; }
        sPsq[threadIdx.x] = s;
    }
    __syncthreads();

    int i = blockIdx.x * blockDim.x + threadIdx.x;
    if (i >= n) return;

    float dot[16];
#pragma unroll
    for (int j = 0; j < 16; j++) dot[j] = 0.f;
    float hh = 0.f;
    const float* h = H + (size_t)i * 64;
    for (int k = 0; k < 64; k++) {
        float hv = h[k];
        hh = fmaf(hv, hv, hh);
#pragma unroll
        for (int j = 0; j < 16; j++) dot[j] = fmaf(hv, sP[j * 64 + k], dot[j]);
    }
    float sim[16];
#pragma unroll
    for (int j = 0; j < 16; j++) {
        float d2 = hh + sPsq[j] - 2.f * dot[j];
        d2 = d2 > 0.f ? d2 : 0.f;
        sim[j] = logf((d2 + 1.0f) / (d2 + 1e-4f));
    }
    float o = sb1;
#pragma unroll
    for (int m = 0; m < 8; m++) {
        float t = sb0[m];
#pragma unroll
        for (int j = 0; j < 16; j++) t = fmaf(sim[j], sW0[j * 8 + m], t);
        float z = 0.5f * t * (1.0f + erff(t * 0.70710678118654752f));  // exact GELU
        o = fmaf(z, sW1[m], o);
    }
    out[i] = 1.0f / (1.0f + expf(-o));

    if (out_size >= 2 * n) {
        float yv = g_is64 ? (float)((const long long*)y)[i]
                          : (float)((const int*)y)[i];
        out[n + i] = yv;
    }
}

// ---------------- launch (single stream, R4 ordering) ----------------
extern "C" void kernel_launch(void* const* d_in, const int* in_sizes, int n_in,
                              void* d_out, int out_size) {
    const float* x    = (const float*)d_in[0];
    const void*  ei   = d_in[1];
    const void*  y    = d_in[2];
    const float* W1   = (const float*)d_in[3];
    const float* b1   = (const float*)d_in[4];
    const float* W2   = (const float*)d_in[5];
    const float* b2   = (const float*)d_in[6];
    const float* W3   = (const float*)d_in[7];
    const float* b3   = (const float*)d_in[8];
    const float* prot = (const float*)d_in[9];
    const float* Wf0  = (const float*)d_in[10];
    const float* bf0  = (const float*)d_in[11];
    const float* Wf1  = (const float*)d_in[12];
    const float* bf1  = (const float*)d_in[13];
    float* out = (float*)d_out;

    int n = in_sizes[0] / 128;
    int E = in_sizes[1] / 2;
    int nb = (n + SCAN_B - 1) / SCAN_B;

    void *pZ, *pH;
    cudaGetSymbolAddress(&pZ, g_Z);
    cudaGetSymbolAddress(&pH, g_H);
    float* Z = (float*)pZ;
    float* H = (float*)pH;

    detect_k<<<1, 256>>>((const int*)ei);
    init_k<<<(n + 255) / 256, 256>>>(n);
    count_k<<<(E + 255) / 256, 256>>>(ei, E);
    scan1_k<<<nb, SCAN_B>>>(n);
    scan2_k<<<1, 64>>>(nb);
    scan3_k<<<(n + 255) / 256, 256>>>(n, nb);
    fill_k<<<(E + 255) / 256, 256>>>(ei, E);

    int gemm_grid = (n + 31) / 32;           // 8 warps * 4 rows per block
    int agg_grid  = (n + 7) / 8;

    gemm_k<128, 128><<<gemm_grid, 256>>>(x, W1, Z, n);
    agg_k<128><<<agg_grid, 256>>>(Z, H, b1, n);
    gemm_k<128, 64><<<gemm_grid, 256>>>(H, W2, Z, n);
    agg_k<64><<<agg_grid, 256>>>(Z, H, b2, n);
    gemm_k<64, 64><<<gemm_grid, 256>>>(H, W3, Z, n);
    agg_k<64><<<agg_grid, 256>>>(Z, H, b3, n);

    final_k<<<(n + 127) / 128, 128>>>(H, prot, Wf0, bf0, Wf1, bf1, y, out, n, out_size);
}

// round 9
// speedup vs baseline: 1.3949x; 1.0504x over previous
#include <cuda_runtime.h>
#include <math.h>

#define NN_MAX 50000
#define NE_MAX 800000
#define SCAN_B 1024

typedef unsigned long long ull;

// ---------------- f32x2 packed helpers (sm_103a) ----------------
__device__ __forceinline__ ull fma2(ull a, ull b, ull c) {
    ull d;
    asm("fma.rn.f32x2 %0, %1, %2, %3;" : "=l"(d) : "l"(a), "l"(b), "l"(c));
    return d;
}
__device__ __forceinline__ ull pack2(float x) {
    ull d;
    unsigned int u = __float_as_uint(x);
    asm("mov.b64 %0, {%1, %2};" : "=l"(d) : "r"(u), "r"(u));
    return d;
}

// ---------------- device scratch (static, allocation-free) ----------------
__device__ float g_Z[(size_t)NN_MAX * 128];
__device__ float g_H[(size_t)NN_MAX * 128];
__device__ float g_dinv[NN_MAX];
__device__ int   g_count[NN_MAX];
__device__ int   g_cursor[NN_MAX];
__device__ int   g_off[NN_MAX + 1];
__device__ int   g_src[NE_MAX];
__device__ float g_w[NE_MAX];
__device__ int   g_blk[64];
__device__ int   g_is64;

__device__ __forceinline__ int edge_val(const void* ei, int E, int which, int e) {
    if (g_is64) return (int)((const long long*)ei)[(size_t)which * E + e];
    return ((const int*)ei)[(size_t)which * E + e];
}

__global__ void detect_k(const int* __restrict__ ei) {
    __shared__ int any;
    if (threadIdx.x == 0) any = 0;
    __syncthreads();
    int local = 0;
    for (int i = threadIdx.x; i < 1024; i += blockDim.x)
        if (ei[2 * i + 1] != 0) local = 1;
    if (local) atomicOr(&any, 1);
    __syncthreads();
    if (threadIdx.x == 0) g_is64 = any ? 0 : 1;
}

__global__ void init_k(int n) {
    int i = blockIdx.x * blockDim.x + threadIdx.x;
    if (i < n) g_count[i] = 0;
}

__global__ void count_k(const void* __restrict__ ei, int E) {
    int e = blockIdx.x * blockDim.x + threadIdx.x;
    if (e < E) atomicAdd(&g_count[edge_val(ei, E, 1, e)], 1);
}

// shuffle-based block scan (exclusive) + dinv
__global__ void scan1_k(int n) {
    __shared__ int wsum[32];
    int tid = threadIdx.x, lane = tid & 31, warp = tid >> 5;
    int i = blockIdx.x * SCAN_B + tid;
    int v = (i < n) ? g_count[i] : 0;
    if (i < n) g_dinv[i] = rsqrtf((float)(v + 1));
    // inclusive warp scan
    int s = v;
#pragma unroll
    for (int off = 1; off < 32; off <<= 1) {
        int t = __shfl_up_sync(0xffffffffu, s, off);
        if (lane >= off) s += t;
    }
    if (lane == 31) wsum[warp] = s;
    __syncthreads();
    if (warp == 0) {
        int ws = wsum[lane];
#pragma unroll
        for (int off = 1; off < 32; off <<= 1) {
            int t = __shfl_up_sync(0xffffffffu, ws, off);
            if (lane >= off) ws += t;
        }
        wsum[lane] = ws;
    }
    __syncthreads();
    int base = (warp > 0) ? wsum[warp - 1] : 0;
    if (i < n) g_off[i] = base + s - v;              // exclusive
    if (tid == SCAN_B - 1) g_blk[blockIdx.x] = wsum[31];
}

__global__ void scan2_k(int nb) {
    __shared__ int sh[64];
    int t = threadIdx.x;
    sh[t] = (t < nb) ? g_blk[t] : 0;
    __syncthreads();
    for (int off = 1; off < 64; off <<= 1) {
        int v = (t >= off) ? sh[t - off] : 0;
        __syncthreads();
        sh[t] += v;
        __syncthreads();
    }
    g_blk[t] = sh[t];
}

// uniform add + cursor init; set g_off[n]
__global__ void scan3_k(int n, int nb) {
    int i = blockIdx.x * blockDim.x + threadIdx.x;
    if (i < n) {
        int blk = i >> 10;
        int o = g_off[i] + ((blk > 0) ? g_blk[blk - 1] : 0);
        g_off[i] = o;
        g_cursor[i] = o;
    }
    if (i == 0) g_off[n] = g_blk[nb - 1];
}

__global__ void fill_k(const void* __restrict__ ei, int E) {
    int e = blockIdx.x * blockDim.x + threadIdx.x;
    if (e < E) {
        int dst = edge_val(ei, E, 1, e);
        int src = edge_val(ei, E, 0, e);
        int p = atomicAdd(&g_cursor[dst], 1);
        g_src[p] = src;
        g_w[p] = g_dinv[src] * g_dinv[dst];
    }
}

// ---------------- f32x2 SIMT GEMM: C[M,N] = A[M,K] @ W[K,N] ----------------
// 256 threads = 8 warps, 4 rows per warp; arithmetic via FFMA2. (R6, frozen)
template<int K, int N>
__global__ void __launch_bounds__(256) gemm_k(const float* __restrict__ A,
                                              const float* __restrict__ W,
                                              float* __restrict__ C, int M) {
    constexpr int CP = N / 32;
    constexpr int PR = CP / 2;
    constexpr int KC = (K * N <= 8192) ? K : (8192 / N);
    __shared__ float sW[KC * N];
    int warp = threadIdx.x >> 5, lane = threadIdx.x & 31;
    int r0 = (blockIdx.x * 8 + warp) * 4;

    ull acc[4][PR];
#pragma unroll
    for (int r = 0; r < 4; r++)
#pragma unroll
        for (int p = 0; p < PR; p++) acc[r][p] = 0ULL;

    for (int kc = 0; kc < K; kc += KC) {
        __syncthreads();
        {
            const float4* Wv = (const float4*)(W + (size_t)kc * N);
            float4* sWv = (float4*)sW;
            for (int i = threadIdx.x; i < KC * N / 4; i += 256) sWv[i] = Wv[i];
        }
        __syncthreads();
        if (r0 < M) {
            int rr[4];
#pragma unroll
            for (int r = 0; r < 4; r++) { int v = r0 + r; rr[r] = v < M ? v : M - 1; }
#pragma unroll 2
            for (int kk = 0; kk < KC; kk += 4) {
                float4 a[4];
#pragma unroll
                for (int r = 0; r < 4; r++)
                    a[r] = *(const float4*)(A + (size_t)rr[r] * K + kc + kk);
#pragma unroll
                for (int t = 0; t < 4; t++) {
                    const ull* wp = (const ull*)&sW[(kk + t) * N + lane * CP];
                    ull w0 = wp[0];
                    ull w1 = (PR == 2) ? wp[1] : 0ULL;
#pragma unroll
                    for (int r = 0; r < 4; r++) {
                        float av = (t == 0) ? a[r].x : (t == 1) ? a[r].y
                                 : (t == 2) ? a[r].z : a[r].w;
                        ull av2 = pack2(av);
                        acc[r][0] = fma2(av2, w0, acc[r][0]);
                        if (PR == 2) acc[r][1] = fma2(av2, w1, acc[r][1]);
                    }
                }
            }
        }
    }
#pragma unroll
    for (int r = 0; r < 4; r++) {
        if (r0 + r < M) {
            ull* cp = (ull*)(C + (size_t)(r0 + r) * N + lane * CP);
            cp[0] = acc[r][0];
            if (PR == 2) cp[1] = acc[r][1];
        }
    }
}

// ---------------- edge aggregation (R6, frozen) ----------------
template<int N>
__global__ void agg_k(const float* __restrict__ Z, float* __restrict__ H,
                      const float* __restrict__ b, int n) {
    constexpr int CP = N / 32;
    int node = (blockIdx.x * blockDim.x + threadIdx.x) >> 5;
    int lane = threadIdx.x & 31;
    if (node >= n) return;
    float di = g_dinv[node];
    float acc[CP];
    {
        float w = di * di;
        const float* zp = Z + (size_t)node * N + lane * CP;
        if (CP == 4) {
            float4 zv = *(const float4*)zp;
            acc[0] = w * zv.x; acc[1] = w * zv.y;
            acc[2] = w * zv.z; acc[3] = w * zv.w;
        } else {
            float2 zv = *(const float2*)zp;
            acc[0] = w * zv.x; acc[1] = w * zv.y;
        }
    }
    int e = g_off[node], end = g_off[node + 1];
    for (; e + 4 <= end; e += 4) {
        int s0 = g_src[e], s1 = g_src[e + 1], s2 = g_src[e + 2], s3 = g_src[e + 3];
        float w0 = g_w[e], w1 = g_w[e + 1], w2 = g_w[e + 2], w3 = g_w[e + 3];
        if (CP == 4) {
            float4 a0 = *(const float4*)(Z + (size_t)s0 * N + lane * 4);
            float4 a1 = *(const float4*)(Z + (size_t)s1 * N + lane * 4);
            float4 a2 = *(const float4*)(Z + (size_t)s2 * N + lane * 4);
            float4 a3 = *(const float4*)(Z + (size_t)s3 * N + lane * 4);
            acc[0] = fmaf(w0, a0.x, acc[0]); acc[1] = fmaf(w0, a0.y, acc[1]);
            acc[2] = fmaf(w0, a0.z, acc[2]); acc[3] = fmaf(w0, a0.w, acc[3]);
            acc[0] = fmaf(w1, a1.x, acc[0]); acc[1] = fmaf(w1, a1.y, acc[1]);
            acc[2] = fmaf(w1, a1.z, acc[2]); acc[3] = fmaf(w1, a1.w, acc[3]);
            acc[0] = fmaf(w2, a2.x, acc[0]); acc[1] = fmaf(w2, a2.y, acc[1]);
            acc[2] = fmaf(w2, a2.z, acc[2]); acc[3] = fmaf(w2, a2.w, acc[3]);
            acc[0] = fmaf(w3, a3.x, acc[0]); acc[1] = fmaf(w3, a3.y, acc[1]);
            acc[2] = fmaf(w3, a3.z, acc[2]); acc[3] = fmaf(w3, a3.w, acc[3]);
        } else {
            float2 a0 = *(const float2*)(Z + (size_t)s0 * N + lane * 2);
            float2 a1 = *(const float2*)(Z + (size_t)s1 * N + lane * 2);
            float2 a2 = *(const float2*)(Z + (size_t)s2 * N + lane * 2);
            float2 a3 = *(const float2*)(Z + (size_t)s3 * N + lane * 2);
            acc[0] = fmaf(w0, a0.x, acc[0]); acc[1] = fmaf(w0, a0.y, acc[1]);
            acc[0] = fmaf(w1, a1.x, acc[0]); acc[1] = fmaf(w1, a1.y, acc[1]);
            acc[0] = fmaf(w2, a2.x, acc[0]); acc[1] = fmaf(w2, a2.y, acc[1]);
            acc[0] = fmaf(w3, a3.x, acc[0]); acc[1] = fmaf(w3, a3.y, acc[1]);
        }
    }
    for (; e < end; e++) {
        int s = g_src[e];
        float w = g_w[e];
        const float* zp = Z + (size_t)s * N + lane * CP;
        if (CP == 4) {
            float4 zv = *(const float4*)zp;
            acc[0] = fmaf(w, zv.x, acc[0]); acc[1] = fmaf(w, zv.y, acc[1]);
            acc[2] = fmaf(w, zv.z, acc[2]); acc[3] = fmaf(w, zv.w, acc[3]);
        } else {
            float2 zv = *(const float2*)zp;
            acc[0] = fmaf(w, zv.x, acc[0]); acc[1] = fmaf(w, zv.y, acc[1]);
        }
    }
#pragma unroll
    for (int j = 0; j < CP; j++) {
        float v = acc[j] + __ldg(&b[lane * CP + j]);
        H[(size_t)node * N + lane * CP + j] = v > 0.f ? v : 0.f;
    }
}

// ---------------- prototype distances + MLP readout + sigmoid + y ---------
__global__ void final_k(const float* __restrict__ H, const float* __restrict__ prot,
                        const float* __restrict__ Wf0, const float* __restrict__ bf0,
                        const float* __restrict__ Wf1, const float* __restrict__ bf1,
                        const void* __restrict__ y,
                        float* __restrict__ out, int n, int out_size) {
    __shared__ float sP[16 * 64];
    __shared__ float sPsq[16];
    __shared__ float sW0[16 * 8];
    __shared__ float sb0[8];
    __shared__ float sW1[8];
    __shared__ float sb1;
    for (int i = threadIdx.x; i < 16 * 64; i += blockDim.x) sP[i] = prot[i];
    if (threadIdx.x < 16 * 8) sW0[threadIdx.x] = Wf0[threadIdx.x];
    if (threadIdx.x < 8) { sb0[threadIdx.x] = bf0[threadIdx.x]; sW1[threadIdx.x] = Wf1[threadIdx.x]; }
    if (threadIdx.x == 0) sb1 = bf1[0];
    __syncthreads();
    if (threadIdx.x < 16) {
        float s = 0.f;
        for (int k = 0; k < 64; k++) { float p = sP[threadIdx.x * 64 + k]; s += p * p; }
        sPsq[threadIdx.x] = s;
    }
    __syncthreads();

    int i = blockIdx.x * blockDim.x + threadIdx.x;
    if (i >= n) return;

    float dot[16];
#pragma unroll
    for (int j = 0; j < 16; j++) dot[j] = 0.f;
    float hh = 0.f;
    const float* h = H + (size_t)i * 64;
    for (int k = 0; k < 64; k++) {
        float hv = h[k];
        hh = fmaf(hv, hv, hh);
#pragma unroll
        for (int j = 0; j < 16; j++) dot[j] = fmaf(hv, sP[j * 64 + k], dot[j]);
    }
    float sim[16];
#pragma unroll
    for (int j = 0; j < 16; j++) {
        float d2 = hh + sPsq[j] - 2.f * dot[j];
        d2 = d2 > 0.f ? d2 : 0.f;
        sim[j] = logf((d2 + 1.0f) / (d2 + 1e-4f));
    }
    float o = sb1;
#pragma unroll
    for (int m = 0; m < 8; m++) {
        float t = sb0[m];
#pragma unroll
        for (int j = 0; j < 16; j++) t = fmaf(sim[j], sW0[j * 8 + m], t);
        float z = 0.5f * t * (1.0f + erff(t * 0.70710678118654752f));  // exact GELU
        o = fmaf(z, sW1[m], o);
    }
    out[i] = 1.0f / (1.0f + expf(-o));

    if (out_size >= 2 * n) {
        float yv = g_is64 ? (float)((const long long*)y)[i]
                          : (float)((const int*)y)[i];
        out[n + i] = yv;
    }
}

// ---------------- launch: CSR on main, gemm1 forked to side stream --------
extern "C" void kernel_launch(void* const* d_in, const int* in_sizes, int n_in,
                              void* d_out, int out_size) {
    const float* x    = (const float*)d_in[0];
    const void*  ei   = d_in[1];
    const void*  y    = d_in[2];
    const float* W1   = (const float*)d_in[3];
    const float* b1   = (const float*)d_in[4];
    const float* W2   = (const float*)d_in[5];
    const float* b2   = (const float*)d_in[6];
    const float* W3   = (const float*)d_in[7];
    const float* b3   = (const float*)d_in[8];
    const float* prot = (const float*)d_in[9];
    const float* Wf0  = (const float*)d_in[10];
    const float* bf0  = (const float*)d_in[11];
    const float* Wf1  = (const float*)d_in[12];
    const float* bf1  = (const float*)d_in[13];
    float* out = (float*)d_out;

    int n = in_sizes[0] / 128;
    int E = in_sizes[1] / 2;
    int nb = (n + SCAN_B - 1) / SCAN_B;

    void *pZ, *pH;
    cudaGetSymbolAddress(&pZ, g_Z);
    cudaGetSymbolAddress(&pH, g_H);
    float* Z = (float*)pZ;
    float* H = (float*)pH;

    int gemm_grid = (n + 31) / 32;
    int agg_grid  = (n + 7) / 8;

    cudaStream_t s2;
    cudaStreamCreateWithFlags(&s2, cudaStreamNonBlocking);
    cudaEvent_t evFork, evJoin;
    cudaEventCreateWithFlags(&evFork, cudaEventDisableTiming);
    cudaEventCreateWithFlags(&evJoin, cudaEventDisableTiming);

    // fork: gemm1 (x only) on side stream
    cudaEventRecord(evFork, 0);
    cudaStreamWaitEvent(s2, evFork, 0);
    gemm_k<128, 128><<<gemm_grid, 256, 0, s2>>>(x, W1, Z, n);
    cudaEventRecord(evJoin, s2);

    // CSR build (edge_index only) on main stream
    detect_k<<<1, 256>>>((const int*)ei);
    init_k<<<(n + 255) / 256, 256>>>(n);
    count_k<<<(E + 255) / 256, 256>>>(ei, E);
    scan1_k<<<nb, SCAN_B>>>(n);
    scan2_k<<<1, 64>>>(nb);
    scan3_k<<<(n + 255) / 256, 256>>>(n, nb);
    fill_k<<<(E + 255) / 256, 256>>>(ei, E);

    // join: agg1 needs both Z and CSR
    cudaStreamWaitEvent(0, evJoin, 0);

    agg_k<128><<<agg_grid, 256>>>(Z, H, b1, n);
    gemm_k<128, 64><<<gemm_grid, 256>>>(H, W2, Z, n);
    agg_k<64><<<agg_grid, 256>>>(Z, H, b2, n);
    gemm_k<64, 64><<<gemm_grid, 256>>>(H, W3, Z, n);
    agg_k<64><<<agg_grid, 256>>>(Z, H, b3, n);

    final_k<<<(n + 127) / 128, 128>>>(H, prot, Wf0, bf0, Wf1, bf1, y, out, n, out_size);
}

// round 10
// speedup vs baseline: 1.5152x; 1.0862x over previous
#include <cuda_runtime.h>
#include <cuda_fp16.h>
#include <math.h>

#define NN_MAX 50000
#define NE_MAX 800000
#define SCAN_B 1024

typedef unsigned long long ull;

// ---------------- f32x2 packed helpers (sm_103a) ----------------
__device__ __forceinline__ ull fma2(ull a, ull b, ull c) {
    ull d;
    asm("fma.rn.f32x2 %0, %1, %2, %3;" : "=l"(d) : "l"(a), "l"(b), "l"(c));
    return d;
}
__device__ __forceinline__ ull pack2(float x) {
    ull d;
    unsigned int u = __float_as_uint(x);
    asm("mov.b64 %0, {%1, %2};" : "=l"(d) : "r"(u), "r"(u));
    return d;
}
__device__ __forceinline__ float2 unpack2(ull v) {
    unsigned int lo, hi;
    asm("mov.b64 {%0, %1}, %2;" : "=r"(lo), "=r"(hi) : "l"(v));
    return make_float2(__uint_as_float(lo), __uint_as_float(hi));
}

// ---------------- device scratch (static, allocation-free) ----------------
__device__ float g_Z[(size_t)NN_MAX * 128];   // fp16 payload lives here (reinterpret)
__device__ float g_H[(size_t)NN_MAX * 128];
__device__ float g_dinv[NN_MAX];
__device__ int   g_count[NN_MAX];
__device__ int   g_cursor[NN_MAX];
__device__ int   g_off[NN_MAX + 1];
__device__ int   g_src[NE_MAX];
__device__ float g_w[NE_MAX];
__device__ int   g_blk[64];
__device__ int   g_is64;

__device__ __forceinline__ int edge_val(const void* ei, int E, int which, int e) {
    if (g_is64) return (int)((const long long*)ei)[(size_t)which * E + e];
    return ((const int*)ei)[(size_t)which * E + e];
}

__global__ void detect_k(const int* __restrict__ ei) {
    __shared__ int any;
    if (threadIdx.x == 0) any = 0;
    __syncthreads();
    int local = 0;
    for (int i = threadIdx.x; i < 1024; i += blockDim.x)
        if (ei[2 * i + 1] != 0) local = 1;
    if (local) atomicOr(&any, 1);
    __syncthreads();
    if (threadIdx.x == 0) g_is64 = any ? 0 : 1;
}

__global__ void init_k(int n) {
    int i = blockIdx.x * blockDim.x + threadIdx.x;
    if (i < n) g_count[i] = 0;
}

__global__ void count_k(const void* __restrict__ ei, int E) {
    int e = blockIdx.x * blockDim.x + threadIdx.x;
    if (e < E) atomicAdd(&g_count[edge_val(ei, E, 1, e)], 1);
}

// shuffle-based block scan (exclusive) + dinv
__global__ void scan1_k(int n) {
    __shared__ int wsum[32];
    int tid = threadIdx.x, lane = tid & 31, warp = tid >> 5;
    int i = blockIdx.x * SCAN_B + tid;
    int v = (i < n) ? g_count[i] : 0;
    if (i < n) g_dinv[i] = rsqrtf((float)(v + 1));
    int s = v;
#pragma unroll
    for (int off = 1; off < 32; off <<= 1) {
        int t = __shfl_up_sync(0xffffffffu, s, off);
        if (lane >= off) s += t;
    }
    if (lane == 31) wsum[warp] = s;
    __syncthreads();
    if (warp == 0) {
        int ws = wsum[lane];
#pragma unroll
        for (int off = 1; off < 32; off <<= 1) {
            int t = __shfl_up_sync(0xffffffffu, ws, off);
            if (lane >= off) ws += t;
        }
        wsum[lane] = ws;
    }
    __syncthreads();
    int base = (warp > 0) ? wsum[warp - 1] : 0;
    if (i < n) g_off[i] = base + s - v;
    if (tid == SCAN_B - 1) g_blk[blockIdx.x] = wsum[31];
}

// merged scan2+scan3: each block scans the <=64 block sums locally (warp 0),
// then applies the uniform add + cursor init.
__global__ void scan23_k(int n, int nb) {
    __shared__ int pre[64];
    int tid = threadIdx.x;
    if (tid < 64) {
        int lane = tid;
        int ws = (lane < nb) ? g_blk[lane] : 0;
        // 2-warp-free inclusive scan over 64 via warp shuffles (2 warps)
        int l5 = lane & 31, w = lane >> 5;
        int s = ws;
#pragma unroll
        for (int off = 1; off < 32; off <<= 1) {
            int t = __shfl_up_sync(0xffffffffu, s, off);
            if (l5 >= off) s += t;
        }
        pre[lane] = s;
        __syncthreads();
        if (w == 1) pre[lane] = s + pre[31];
        __syncthreads();
    } else {
        __syncthreads();
        __syncthreads();
    }
    int i = blockIdx.x * blockDim.x + tid;
    if (i < n) {
        int blk = i >> 10;
        int o = g_off[i] + ((blk > 0) ? pre[blk - 1] : 0);
        g_off[i] = o;
        g_cursor[i] = o;
    }
    if (i == 0) g_off[n] = pre[nb - 1];
}

__global__ void fill_k(const void* __restrict__ ei, int E) {
    int e = blockIdx.x * blockDim.x + threadIdx.x;
    if (e < E) {
        int dst = edge_val(ei, E, 1, e);
        int src = edge_val(ei, E, 0, e);
        int p = atomicAdd(&g_cursor[dst], 1);
        g_src[p] = src;
        g_w[p] = g_dinv[src] * g_dinv[dst];
    }
}

// ---------------- f32x2 SIMT GEMM: C[M,N](fp16) = A[M,K](fp32) @ W[K,N] ----
// 256 threads = 8 warps, 4 rows per warp; arithmetic via FFMA2; fp16 store.
template<int K, int N>
__global__ void __launch_bounds__(256) gemm_k(const float* __restrict__ A,
                                              const float* __restrict__ W,
                                              __half* __restrict__ C, int M) {
    constexpr int CP = N / 32;
    constexpr int PR = CP / 2;
    constexpr int KC = (K * N <= 8192) ? K : (8192 / N);
    __shared__ float sW[KC * N];
    int warp = threadIdx.x >> 5, lane = threadIdx.x & 31;
    int r0 = (blockIdx.x * 8 + warp) * 4;

    ull acc[4][PR];
#pragma unroll
    for (int r = 0; r < 4; r++)
#pragma unroll
        for (int p = 0; p < PR; p++) acc[r][p] = 0ULL;

    for (int kc = 0; kc < K; kc += KC) {
        __syncthreads();
        {
            const float4* Wv = (const float4*)(W + (size_t)kc * N);
            float4* sWv = (float4*)sW;
            for (int i = threadIdx.x; i < KC * N / 4; i += 256) sWv[i] = Wv[i];
        }
        __syncthreads();
        if (r0 < M) {
            int rr[4];
#pragma unroll
            for (int r = 0; r < 4; r++) { int v = r0 + r; rr[r] = v < M ? v : M - 1; }
#pragma unroll 2
            for (int kk = 0; kk < KC; kk += 4) {
                float4 a[4];
#pragma unroll
                for (int r = 0; r < 4; r++)
                    a[r] = *(const float4*)(A + (size_t)rr[r] * K + kc + kk);
#pragma unroll
                for (int t = 0; t < 4; t++) {
                    const ull* wp = (const ull*)&sW[(kk + t) * N + lane * CP];
                    ull w0 = wp[0];
                    ull w1 = (PR == 2) ? wp[1] : 0ULL;
#pragma unroll
                    for (int r = 0; r < 4; r++) {
                        float av = (t == 0) ? a[r].x : (t == 1) ? a[r].y
                                 : (t == 2) ? a[r].z : a[r].w;
                        ull av2 = pack2(av);
                        acc[r][0] = fma2(av2, w0, acc[r][0]);
                        if (PR == 2) acc[r][1] = fma2(av2, w1, acc[r][1]);
                    }
                }
            }
        }
    }
#pragma unroll
    for (int r = 0; r < 4; r++) {
        if (r0 + r < M) {
            __half* cp = C + (size_t)(r0 + r) * N + lane * CP;
            float2 f0 = unpack2(acc[r][0]);
            __half2 h0 = __float22half2_rn(f0);
            if (PR == 2) {
                float2 f1 = unpack2(acc[r][1]);
                __half2 h1 = __float22half2_rn(f1);
                uint2 st;
                st.x = *reinterpret_cast<unsigned int*>(&h0);
                st.y = *reinterpret_cast<unsigned int*>(&h1);
                *(uint2*)cp = st;
            } else {
                *(__half2*)cp = h0;
            }
        }
    }
}

// ---------------- edge aggregation: H = relu(sum w_e * Z[src](fp16) + b) ----
__device__ __forceinline__ float4 ldZ4(const __half* p) {
    uint2 u = *(const uint2*)p;
    __half2 h0 = *reinterpret_cast<__half2*>(&u.x);
    __half2 h1 = *reinterpret_cast<__half2*>(&u.y);
    float2 a = __half22float2(h0), b = __half22float2(h1);
    return make_float4(a.x, a.y, b.x, b.y);
}
__device__ __forceinline__ float2 ldZ2(const __half* p) {
    __half2 h = *(const __half2*)p;
    return __half22float2(h);
}

template<int N>
__global__ void agg_k(const __half* __restrict__ Z, float* __restrict__ H,
                      const float* __restrict__ b, int n) {
    constexpr int CP = N / 32;
    int node = (blockIdx.x * blockDim.x + threadIdx.x) >> 5;
    int lane = threadIdx.x & 31;
    if (node >= n) return;
    float di = g_dinv[node];
    float acc[CP];
    {
        float w = di * di;  // self loop
        const __half* zp = Z + (size_t)node * N + lane * CP;
        if (CP == 4) {
            float4 zv = ldZ4(zp);
            acc[0] = w * zv.x; acc[1] = w * zv.y;
            acc[2] = w * zv.z; acc[3] = w * zv.w;
        } else {
            float2 zv = ldZ2(zp);
            acc[0] = w * zv.x; acc[1] = w * zv.y;
        }
    }
    int e = g_off[node], end = g_off[node + 1];
    for (; e + 4 <= end; e += 4) {
        int s0 = g_src[e], s1 = g_src[e + 1], s2 = g_src[e + 2], s3 = g_src[e + 3];
        float w0 = g_w[e], w1 = g_w[e + 1], w2 = g_w[e + 2], w3 = g_w[e + 3];
        if (CP == 4) {
            float4 a0 = ldZ4(Z + (size_t)s0 * N + lane * 4);
            float4 a1 = ldZ4(Z + (size_t)s1 * N + lane * 4);
            float4 a2 = ldZ4(Z + (size_t)s2 * N + lane * 4);
            float4 a3 = ldZ4(Z + (size_t)s3 * N + lane * 4);
            acc[0] = fmaf(w0, a0.x, acc[0]); acc[1] = fmaf(w0, a0.y, acc[1]);
            acc[2] = fmaf(w0, a0.z, acc[2]); acc[3] = fmaf(w0, a0.w, acc[3]);
            acc[0] = fmaf(w1, a1.x, acc[0]); acc[1] = fmaf(w1, a1.y, acc[1]);
            acc[2] = fmaf(w1, a1.z, acc[2]); acc[3] = fmaf(w1, a1.w, acc[3]);
            acc[0] = fmaf(w2, a2.x, acc[0]); acc[1] = fmaf(w2, a2.y, acc[1]);
            acc[2] = fmaf(w2, a2.z, acc[2]); acc[3] = fmaf(w2, a2.w, acc[3]);
            acc[0] = fmaf(w3, a3.x, acc[0]); acc[1] = fmaf(w3, a3.y, acc[1]);
            acc[2] = fmaf(w3, a3.z, acc[2]); acc[3] = fmaf(w3, a3.w, acc[3]);
        } else {
            float2 a0 = ldZ2(Z + (size_t)s0 * N + lane * 2);
            float2 a1 = ldZ2(Z + (size_t)s1 * N + lane * 2);
            float2 a2 = ldZ2(Z + (size_t)s2 * N + lane * 2);
            float2 a3 = ldZ2(Z + (size_t)s3 * N + lane * 2);
            acc[0] = fmaf(w0, a0.x, acc[0]); acc[1] = fmaf(w0, a0.y, acc[1]);
            acc[0] = fmaf(w1, a1.x, acc[0]); acc[1] = fmaf(w1, a1.y, acc[1]);
            acc[0] = fmaf(w2, a2.x, acc[0]); acc[1] = fmaf(w2, a2.y, acc[1]);
            acc[0] = fmaf(w3, a3.x, acc[0]); acc[1] = fmaf(w3, a3.y, acc[1]);
        }
    }
    for (; e < end; e++) {
        int s = g_src[e];
        float w = g_w[e];
        const __half* zp = Z + (size_t)s * N + lane * CP;
        if (CP == 4) {
            float4 zv = ldZ4(zp);
            acc[0] = fmaf(w, zv.x, acc[0]); acc[1] = fmaf(w, zv.y, acc[1]);
            acc[2] = fmaf(w, zv.z, acc[2]); acc[3] = fmaf(w, zv.w, acc[3]);
        } else {
            float2 zv = ldZ2(zp);
            acc[0] = fmaf(w, zv.x, acc[0]); acc[1] = fmaf(w, zv.y, acc[1]);
        }
    }
#pragma unroll
    for (int j = 0; j < CP; j++) {
        float v = acc[j] + __ldg(&b[lane * CP + j]);
        H[(size_t)node * N + lane * CP + j] = v > 0.f ? v : 0.f;
    }
}

// ---------------- prototype distances + MLP readout + sigmoid + y ---------
__global__ void final_k(const float* __restrict__ H, const float* __restrict__ prot,
                        const float* __restrict__ Wf0, const float* __restrict__ bf0,
                        const float* __restrict__ Wf1, const float* __restrict__ bf1,
                        const void* __restrict__ y,
                        float* __restrict__ out, int n, int out_size) {
    __shared__ float sP[16 * 64];
    __shared__ float sPsq[16];
    __shared__ float sW0[16 * 8];
    __shared__ float sb0[8];
    __shared__ float sW1[8];
    __shared__ float sb1;
    for (int i = threadIdx.x; i < 16 * 64; i += blockDim.x) sP[i] = prot[i];
    if (threadIdx.x < 16 * 8) sW0[threadIdx.x] = Wf0[threadIdx.x];
    if (threadIdx.x < 8) { sb0[threadIdx.x] = bf0[threadIdx.x]; sW1[threadIdx.x] = Wf1[threadIdx.x]; }
    if (threadIdx.x == 0) sb1 = bf1[0];
    __syncthreads();
    if (threadIdx.x < 16) {
        float s = 0.f;
        for (int k = 0; k < 64; k++) { float p = sP[threadIdx.x * 64 + k]; s += p * p; }
        sPsq[threadIdx.x] = s;
    }
    __syncthreads();

    int i = blockIdx.x * blockDim.x + threadIdx.x;
    if (i >= n) return;

    float dot[16];
#pragma unroll
    for (int j = 0; j < 16; j++) dot[j] = 0.f;
    float hh = 0.f;
    const float* h = H + (size_t)i * 64;
    for (int k = 0; k < 64; k++) {
        float hv = h[k];
        hh = fmaf(hv, hv, hh);
#pragma unroll
        for (int j = 0; j < 16; j++) dot[j] = fmaf(hv, sP[j * 64 + k], dot[j]);
    }
    float sim[16];
#pragma unroll
    for (int j = 0; j < 16; j++) {
        float d2 = hh + sPsq[j] - 2.f * dot[j];
        d2 = d2 > 0.f ? d2 : 0.f;
        sim[j] = logf((d2 + 1.0f) / (d2 + 1e-4f));
    }
    float o = sb1;
#pragma unroll
    for (int m = 0; m < 8; m++) {
        float t = sb0[m];
#pragma unroll
        for (int j = 0; j < 16; j++) t = fmaf(sim[j], sW0[j * 8 + m], t);
        float z = 0.5f * t * (1.0f + erff(t * 0.70710678118654752f));  // exact GELU
        o = fmaf(z, sW1[m], o);
    }
    out[i] = 1.0f / (1.0f + expf(-o));

    if (out_size >= 2 * n) {
        float yv = g_is64 ? (float)((const long long*)y)[i]
                          : (float)((const int*)y)[i];
        out[n + i] = yv;
    }
}

// ---------------- launch: CSR on main, gemm1 forked to side stream --------
extern "C" void kernel_launch(void* const* d_in, const int* in_sizes, int n_in,
                              void* d_out, int out_size) {
    const float* x    = (const float*)d_in[0];
    const void*  ei   = d_in[1];
    const void*  y    = d_in[2];
    const float* W1   = (const float*)d_in[3];
    const float* b1   = (const float*)d_in[4];
    const float* W2   = (const float*)d_in[5];
    const float* b2   = (const float*)d_in[6];
    const float* W3   = (const float*)d_in[7];
    const float* b3   = (const float*)d_in[8];
    const float* prot = (const float*)d_in[9];
    const float* Wf0  = (const float*)d_in[10];
    const float* bf0  = (const float*)d_in[11];
    const float* Wf1  = (const float*)d_in[12];
    const float* bf1  = (const float*)d_in[13];
    float* out = (float*)d_out;

    int n = in_sizes[0] / 128;
    int E = in_sizes[1] / 2;
    int nb = (n + SCAN_B - 1) / SCAN_B;

    void *pZ, *pH;
    cudaGetSymbolAddress(&pZ, g_Z);
    cudaGetSymbolAddress(&pH, g_H);
    __half* Z = (__half*)pZ;
    float* H = (float*)pH;

    int gemm_grid = (n + 31) / 32;
    int agg_grid  = (n + 7) / 8;

    cudaStream_t s2;
    cudaStreamCreateWithFlags(&s2, cudaStreamNonBlocking);
    cudaEvent_t evFork, evJoin;
    cudaEventCreateWithFlags(&evFork, cudaEventDisableTiming);
    cudaEventCreateWithFlags(&evJoin, cudaEventDisableTiming);

    // fork: gemm1 (x only) on side stream
    cudaEventRecord(evFork, 0);
    cudaStreamWaitEvent(s2, evFork, 0);
    gemm_k<128, 128><<<gemm_grid, 256, 0, s2>>>(x, W1, Z, n);
    cudaEventRecord(evJoin, s2);

    // CSR build (edge_index only) on main stream
    detect_k<<<1, 256>>>((const int*)ei);
    init_k<<<(n + 255) / 256, 256>>>(n);
    count_k<<<(E + 255) / 256, 256>>>(ei, E);
    scan1_k<<<nb, SCAN_B>>>(n);
    scan23_k<<<(n + 255) / 256, 256>>>(n, nb);
    fill_k<<<(E + 255) / 256, 256>>>(ei, E);

    // join: agg1 needs both Z and CSR
    cudaStreamWaitEvent(0, evJoin, 0);

    agg_k<128><<<agg_grid, 256>>>(Z, H, b1, n);
    gemm_k<128, 64><<<gemm_grid, 256>>>(H, W2, Z, n);
    agg_k<64><<<agg_grid, 256>>>(Z, H, b2, n);
    gemm_k<64, 64><<<gemm_grid, 256>>>(H, W3, Z, n);
    agg_k<64><<<agg_grid, 256>>>(Z, H, b3, n);

    final_k<<<(n + 127) / 128, 128>>>(H, prot, Wf0, bf0, Wf1, bf1, y, out, n, out_size);
}